// round 14
// baseline (speedup 1.0000x reference)
#include <cuda_runtime.h>
#include <math.h>

#define DIMV   512
#define C_NUM  16
#define ALPHA_C 0.1f
#define BETA_C  1.1f
#define EPS_C   1e-8f
#define K2_BLOCKS 512
#define NREP   8                       // k_sums flush replicas (contention 512 -> 64)
#define P2_THREADS 128
#define P2_R 4                         // samples per thread
#define P2_ROWS (P2_THREADS * P2_R)    // 512 rows per block
#define PSTRIDE 516                    // padded centroid row stride in smem

// ------------------- static device scratch (no allocations allowed) -------------------
// Accumulators are zero on first use (BSS) and re-zeroed at the END of every run by
// k_final -> no separate init kernel.
__device__ float g_sums8[NREP * C_NUM * DIMV];   // replicated class sums (256 KB)
__device__ int   g_cnt[C_NUM];
__device__ float g_cnT[DIMV * C_NUM];   // normalized centroids, transposed [d][c]
__device__ float g_cntf[C_NUM];
__device__ float g_deg[C_NUM];
__device__ float g_pm[C_NUM * C_NUM];
__device__ float g_S[C_NUM * C_NUM];
__device__ float g_intra;
__device__ float g_count;
__device__ float g_numpairs;

// packed f32x2 FFMA (PTX-only; ptxas never fuses from C++)
__device__ __forceinline__ void ffma2(unsigned long long& d,
                                      unsigned long long a, unsigned long long b) {
    asm("fma.rn.f32x2 %0, %1, %2, %0;" : "+l"(d) : "l"(a), "l"(b));
}
__device__ __forceinline__ unsigned long long pack2(float lo, float hi) {
    unsigned long long r;
    asm("mov.b64 %0, {%1, %2};" : "=l"(r) : "f"(lo), "f"(hi));
    return r;
}

// ------------------- K2: class sums — 512 blocks, 4-row MLP batching, replica flush ------
// Thread t exclusively owns dims {2t, 2t+1} of every class row -> no atomics in the loop.
__global__ __launch_bounds__(256) void k_sums(const float* __restrict__ emb,
                                              const int* __restrict__ labels, int n) {
    __shared__ float acc[C_NUM * DIMV];   // 32 KB
    __shared__ int   scnt[C_NUM];
    int t = threadIdx.x;
    #pragma unroll
    for (int c = 0; c < C_NUM; c++) {
        acc[c * DIMV + 2 * t]     = 0.f;
        acc[c * DIMV + 2 * t + 1] = 0.f;
    }
    if (t < C_NUM) scnt[t] = 0;
    __syncthreads();

    const float2 z2 = make_float2(0.f, 0.f);
    for (int r = blockIdx.x; r < n; r += 4 * K2_BLOCKS) {
        int r1 = r + K2_BLOCKS, r2 = r + 2 * K2_BLOCKS, r3 = r + 3 * K2_BLOCKS;
        bool b1 = r1 < n, b2 = r2 < n, b3 = r3 < n;
        // batch all independent loads first (MLP=4 data + labels)
        int l0 = __ldg(&labels[r]);
        int l1 = b1 ? __ldg(&labels[r1]) : 0;
        int l2 = b2 ? __ldg(&labels[r2]) : 0;
        int l3 = b3 ? __ldg(&labels[r3]) : 0;
        float2 v0 = *(const float2*)(emb + (size_t)r  * DIMV + 2 * t);
        float2 v1 = b1 ? *(const float2*)(emb + (size_t)r1 * DIMV + 2 * t) : z2;
        float2 v2 = b2 ? *(const float2*)(emb + (size_t)r2 * DIMV + 2 * t) : z2;
        float2 v3 = b3 ? *(const float2*)(emb + (size_t)r3 * DIMV + 2 * t) : z2;
        {
            float2 a = *(float2*)&acc[l0 * DIMV + 2 * t];
            a.x += v0.x; a.y += v0.y;
            *(float2*)&acc[l0 * DIMV + 2 * t] = a;
        }
        if (b1) {
            float2 a = *(float2*)&acc[l1 * DIMV + 2 * t];
            a.x += v1.x; a.y += v1.y;
            *(float2*)&acc[l1 * DIMV + 2 * t] = a;
        }
        if (b2) {
            float2 a = *(float2*)&acc[l2 * DIMV + 2 * t];
            a.x += v2.x; a.y += v2.y;
            *(float2*)&acc[l2 * DIMV + 2 * t] = a;
        }
        if (b3) {
            float2 a = *(float2*)&acc[l3 * DIMV + 2 * t];
            a.x += v3.x; a.y += v3.y;
            *(float2*)&acc[l3 * DIMV + 2 * t] = a;
        }
        if (t == 0) {
            scnt[l0]++;
            if (b1) scnt[l1]++;
            if (b2) scnt[l2]++;
            if (b3) scnt[l3]++;
        }
    }
    __syncthreads();

    float* dst = g_sums8 + (blockIdx.x & (NREP - 1)) * (C_NUM * DIMV);
    for (int i = t; i < C_NUM * DIMV; i += 256) atomicAdd(&dst[i], acc[i]);
    if (t < C_NUM) atomicAdd(&g_cnt[t], scnt[t]);
}

// ------------------- K3: fused centroid normalize + pair analysis (1 block, 512 thr) -----
__global__ __launch_bounds__(512) void k_cent_pairs() {
    __shared__ __align__(16) float sc[C_NUM * PSTRIDE];   // normalized centroids [c][516]
    __shared__ float spm[256];
    __shared__ float sdeg[16];
    __shared__ float scf[16];
    int t = threadIdx.x, w = t >> 5, lane = t & 31;

    // Phase A: warp w owns class w. Each lane: 16 dims strided 32, summed over 8 replicas.
    {
        int c = w;
        float cf = (float)g_cnt[c];
        float mx = fmaxf(cf, 1.f);
        float v[16];
        #pragma unroll
        for (int k = 0; k < 16; k++) v[k] = 0.f;
        #pragma unroll
        for (int rep = 0; rep < NREP; rep++) {
            const float* src = g_sums8 + rep * (C_NUM * DIMV) + c * DIMV;
            #pragma unroll
            for (int k = 0; k < 16; k++)
                v[k] += src[lane + k * 32];   // coalesced 128-B lines, L2-hot
        }
        float sq = 0.f;
        #pragma unroll
        for (int k = 0; k < 16; k++) {
            v[k] /= mx;
            sq += v[k] * v[k];
        }
        #pragma unroll
        for (int o = 16; o > 0; o >>= 1) sq += __shfl_xor_sync(0xFFFFFFFFu, sq, o);
        float inv = 1.f / fmaxf(sqrtf(sq), EPS_C);
        #pragma unroll
        for (int k = 0; k < 16; k++)
            sc[c * PSTRIDE + lane + k * 32] = v[k] * inv;
        if (lane == 0) { scf[c] = cf; g_cntf[c] = cf; }
    }
    __syncthreads();

    // write g_cnT [d][c] coalesced from smem
    for (int i = t; i < C_NUM * DIMV; i += 512) {
        int d = i >> 4, cc = i & 15;
        g_cnT[i] = sc[cc * PSTRIDE + d];
    }

    // Phase B: 256 threads = 16x16 pairs, 4 independent dot partials
    if (t < 256) {
        int i = t >> 4, j = t & 15;
        const float* ri = &sc[i * PSTRIDE];
        const float* rj = &sc[j * PSTRIDE];
        float d0 = 0.f, d1 = 0.f, d2 = 0.f, d3 = 0.f;
        #pragma unroll 4
        for (int d = 0; d < DIMV; d += 16) {
            float4 a0 = *(const float4*)(ri + d);
            float4 b0 = *(const float4*)(rj + d);
            float4 a1 = *(const float4*)(ri + d + 4);
            float4 b1 = *(const float4*)(rj + d + 4);
            float4 a2 = *(const float4*)(ri + d + 8);
            float4 b2 = *(const float4*)(rj + d + 8);
            float4 a3 = *(const float4*)(ri + d + 12);
            float4 b3 = *(const float4*)(rj + d + 12);
            d0 += a0.x * b0.x + a0.y * b0.y + a0.z * b0.z + a0.w * b0.w;
            d1 += a1.x * b1.x + a1.y * b1.y + a1.z * b1.z + a1.w * b1.w;
            d2 += a2.x * b2.x + a2.y * b2.y + a2.z * b2.z + a2.w * b2.w;
            d3 += a3.x * b3.x + a3.y * b3.y + a3.z * b3.z + a3.w * b3.w;
        }
        float dot = (d0 + d1) + (d2 + d3);
        float pd = 1.f - dot;
        float ci = scf[i], cj = scf[j];
        float pm = (i < j && ci > 0.f && cj > 0.f && pd <= BETA_C) ? 1.f : 0.f;
        spm[t] = pm;
        g_pm[t] = pm;
    }
    __syncthreads();
    if (t < 16) {
        float dg = 0.f;
        #pragma unroll
        for (int k = 0; k < 16; k++) dg += spm[t * 16 + k] + spm[k * 16 + t];
        sdeg[t] = dg;
        g_deg[t] = dg;
    }
    __syncthreads();
    if (t == 0) {
        float cnt_total = 0.f, np = 0.f;
        #pragma unroll
        for (int c = 0; c < 16; c++) cnt_total += sdeg[c] * scf[c];
        for (int k = 0; k < 256; k++) np += spm[k];
        g_count = cnt_total;
        g_numpairs = np;
    }
}

// ------------------- probe: no-op to place k_pass2 in ncu's profiled (4th) launch slot ---
__global__ void k_probe() {}

// ------------------- K4: main pass — R13 structure (measured best) -----------------------
__global__ __launch_bounds__(P2_THREADS, 2) void k_pass2(const float* __restrict__ emb,
                                                         const int* __restrict__ labels, int n) {
    __shared__ __align__(16) float s_c[DIMV * C_NUM];   // 32 KB [d][c]
    __shared__ float s_S[C_NUM * C_NUM];
    __shared__ float s_red[4];

    int t = threadIdx.x;
    for (int i = t; i < DIMV * C_NUM / 4; i += P2_THREADS)
        ((float4*)s_c)[i] = ((const float4*)g_cnT)[i];
    s_S[t] = 0.f; s_S[t + 128] = 0.f;
    __syncthreads();

    int row0 = blockIdx.x * P2_ROWS;
    int rows[P2_R];
    #pragma unroll
    for (int s = 0; s < P2_R; s++) rows[s] = row0 + t + s * P2_THREADS;

    unsigned long long acc2[P2_R][8];
    unsigned long long nrm2[P2_R];
    #pragma unroll
    for (int s = 0; s < P2_R; s++) {
        nrm2[s] = 0ull;
        #pragma unroll
        for (int c8 = 0; c8 < 8; c8++) acc2[s][c8] = 0ull;
    }

    const float4 zero4 = make_float4(0.f, 0.f, 0.f, 0.f);
    #pragma unroll 2
    for (int d4 = 0; d4 < DIMV; d4 += 4) {
        float4 xv[P2_R];
        #pragma unroll
        for (int s = 0; s < P2_R; s++)
            xv[s] = (rows[s] < n) ? __ldg((const float4*)(emb + (size_t)rows[s] * DIMV + d4))
                                  : zero4;
        #pragma unroll
        for (int s = 0; s < P2_R; s++) {
            unsigned long long xy = pack2(xv[s].x, xv[s].y);
            unsigned long long zw = pack2(xv[s].z, xv[s].w);
            ffma2(nrm2[s], xy, xy);
            ffma2(nrm2[s], zw, zw);
        }
        const float* cb = &s_c[d4 * C_NUM];
        #pragma unroll
        for (int dd = 0; dd < 4; dd++) {
            ulonglong2 cva = *(const ulonglong2*)(cb + dd * C_NUM + 0);   // classes 0-3
            ulonglong2 cvb = *(const ulonglong2*)(cb + dd * C_NUM + 4);   // classes 4-7
            ulonglong2 cvc = *(const ulonglong2*)(cb + dd * C_NUM + 8);   // classes 8-11
            ulonglong2 cvd = *(const ulonglong2*)(cb + dd * C_NUM + 12);  // classes 12-15
            #pragma unroll
            for (int s = 0; s < P2_R; s++) {
                float xs = (&xv[s].x)[dd];
                unsigned long long xs2 = pack2(xs, xs);
                ffma2(acc2[s][0], xs2, cva.x);
                ffma2(acc2[s][1], xs2, cva.y);
                ffma2(acc2[s][2], xs2, cvb.x);
                ffma2(acc2[s][3], xs2, cvb.y);
                ffma2(acc2[s][4], xs2, cvc.x);
                ffma2(acc2[s][5], xs2, cvc.y);
                ffma2(acc2[s][6], xs2, cvd.x);
                ffma2(acc2[s][7], xs2, cvd.y);
            }
        }
    }

    // epilogue per sample: D[c] = 1 - cn[c]·xn ; fold into intra & S
    float intra_part = 0.f;
    #pragma unroll
    for (int s = 0; s < P2_R; s++) {
        if (rows[s] < n) {
            float accf[16];
            #pragma unroll
            for (int c8 = 0; c8 < 8; c8++)
                asm("mov.b64 {%0, %1}, %2;"
                    : "=f"(accf[2 * c8]), "=f"(accf[2 * c8 + 1]) : "l"(acc2[s][c8]));
            float nlo, nhi;
            asm("mov.b64 {%0, %1}, %2;" : "=f"(nlo), "=f"(nhi) : "l"(nrm2[s]));
            float nrm = nlo + nhi;

            int lbl = __ldg(&labels[rows[s]]);
            float inv = 1.f / fmaxf(sqrtf(nrm), EPS_C);
            float down = 0.f;
            #pragma unroll
            for (int c = 0; c < 16; c++) {
                float D = 1.f - accf[c] * inv;
                float v = BETA_C - D;
                if (v > 0.f) atomicAdd(&s_S[c * 16 + lbl], v);
                if (c == lbl) down = D;
            }
            intra_part += __ldg(&g_deg[lbl]) * fmaxf(down - ALPHA_C, 0.f);
        }
    }

    #pragma unroll
    for (int o = 16; o > 0; o >>= 1)
        intra_part += __shfl_down_sync(0xFFFFFFFFu, intra_part, o);
    if ((t & 31) == 0) s_red[t >> 5] = intra_part;
    __syncthreads();   // orders s_S shared atomics before flush
    if (t == 0)
        atomicAdd(&g_intra, s_red[0] + s_red[1] + s_red[2] + s_red[3]);
    atomicAdd(&g_S[t], s_S[t]);
    atomicAdd(&g_S[t + 128], s_S[t + 128]);
}

// ------------------- K5: final scalar (block 0) + re-zero all accumulators ---------------
__global__ void k_final(float* __restrict__ out) {
    int t = threadIdx.x;   // 256
    if (blockIdx.x == 0) {
        __shared__ float sred[8];
        int i = t >> 4, j = t & 15;
        float v = g_pm[t] * (g_S[t] + g_S[j * 16 + i]);
        #pragma unroll
        for (int o = 16; o > 0; o >>= 1) v += __shfl_down_sync(0xFFFFFFFFu, v, o);
        if ((t & 31) == 0) sred[t >> 5] = v;
        __syncthreads();
        if (t == 0) {
            float inter = 0.f;
            #pragma unroll
            for (int w = 0; w < 8; w++) inter += sred[w];
            float denom = fmaxf(g_count, 1.f);
            out[0] = (g_numpairs > 0.f) ? (g_intra + inter) / denom : 0.f;
        }
        __syncthreads();   // block 0's reads of g_S/g_intra complete before re-zeroing
        g_S[t] = 0.f;
        if (t < C_NUM) g_cnt[t] = 0;
        if (t == 0) g_intra = 0.f;
    } else {
        // blocks 1..NREP zero one replica each (never read by k_final -> no race)
        float* dst = g_sums8 + (blockIdx.x - 1) * (C_NUM * DIMV);
        #pragma unroll
        for (int k = 0; k < C_NUM * DIMV / 256; k++) dst[k * 256 + t] = 0.f;
    }
}

// ------------------- launch -------------------
extern "C" void kernel_launch(void* const* d_in, const int* in_sizes, int n_in,
                              void* d_out, int out_size) {
    const float* emb    = (const float*)d_in[0];
    const int*   labels = (const int*)d_in[1];
    int n = in_sizes[1];

    k_sums<<<K2_BLOCKS, 256>>>(emb, labels, n);
    k_cent_pairs<<<1, 512>>>();
    k_probe<<<1, 32>>>();   // positions k_pass2 as the ncu-profiled (4th) launch
    int blocks = (n + P2_ROWS - 1) / P2_ROWS;
    k_pass2<<<blocks, P2_THREADS>>>(emb, labels, n);
    k_final<<<1 + NREP, 256>>>((float*)d_out);
}

// round 16
// speedup vs baseline: 1.0181x; 1.0181x over previous
#include <cuda_runtime.h>
#include <math.h>

#define DIMV   512
#define C_NUM  16
#define ALPHA_C 0.1f
#define BETA_C  1.1f
#define EPS_C   1e-8f
#define K2_BLOCKS 512
#define NREP   8                       // k_sums flush replicas (contention 512 -> 64)
#define P2_THREADS 128
#define P2_R 4                         // samples per thread
#define P2_ROWS (P2_THREADS * P2_R)    // 512 rows per block
#define CHUNK  32                      // dims staged per iteration
#define XSTR4  9                       // tile row stride in float4 (odd -> conflict-free)
#define PSTRIDE 516                    // padded centroid row stride in k_cent_pairs smem

// ------------------- static device scratch (no allocations allowed) -------------------
// Accumulators are zero on first use (BSS) and re-zeroed at the END of every run by
// k_final -> no separate init kernel.
__device__ float g_sums8[NREP * C_NUM * DIMV];   // replicated class sums (256 KB)
__device__ int   g_cnt[C_NUM];
__device__ float g_cnT[DIMV * C_NUM];   // normalized centroids, transposed [d][c]
__device__ float g_cntf[C_NUM];
__device__ float g_deg[C_NUM];
__device__ float g_pm[C_NUM * C_NUM];
__device__ float g_S[C_NUM * C_NUM];
__device__ float g_intra;
__device__ float g_count;
__device__ float g_numpairs;

// packed f32x2 FFMA (PTX-only; ptxas never fuses from C++)
__device__ __forceinline__ void ffma2(unsigned long long& d,
                                      unsigned long long a, unsigned long long b) {
    asm("fma.rn.f32x2 %0, %1, %2, %0;" : "+l"(d) : "l"(a), "l"(b));
}
__device__ __forceinline__ unsigned long long pack2(float lo, float hi) {
    unsigned long long r;
    asm("mov.b64 %0, {%1, %2};" : "=l"(r) : "f"(lo), "f"(hi));
    return r;
}

// ------------------- K2: class sums — 512 blocks, 4-row MLP batching, replica flush ------
// Thread t exclusively owns dims {2t, 2t+1} of every class row -> no atomics in the loop.
__global__ __launch_bounds__(256) void k_sums(const float* __restrict__ emb,
                                              const int* __restrict__ labels, int n) {
    __shared__ float acc[C_NUM * DIMV];   // 32 KB
    __shared__ int   scnt[C_NUM];
    int t = threadIdx.x;
    #pragma unroll
    for (int c = 0; c < C_NUM; c++) {
        acc[c * DIMV + 2 * t]     = 0.f;
        acc[c * DIMV + 2 * t + 1] = 0.f;
    }
    if (t < C_NUM) scnt[t] = 0;
    __syncthreads();

    const float2 z2 = make_float2(0.f, 0.f);
    for (int r = blockIdx.x; r < n; r += 4 * K2_BLOCKS) {
        int r1 = r + K2_BLOCKS, r2 = r + 2 * K2_BLOCKS, r3 = r + 3 * K2_BLOCKS;
        bool b1 = r1 < n, b2 = r2 < n, b3 = r3 < n;
        int l0 = __ldg(&labels[r]);
        int l1 = b1 ? __ldg(&labels[r1]) : 0;
        int l2 = b2 ? __ldg(&labels[r2]) : 0;
        int l3 = b3 ? __ldg(&labels[r3]) : 0;
        float2 v0 = *(const float2*)(emb + (size_t)r  * DIMV + 2 * t);
        float2 v1 = b1 ? *(const float2*)(emb + (size_t)r1 * DIMV + 2 * t) : z2;
        float2 v2 = b2 ? *(const float2*)(emb + (size_t)r2 * DIMV + 2 * t) : z2;
        float2 v3 = b3 ? *(const float2*)(emb + (size_t)r3 * DIMV + 2 * t) : z2;
        {
            float2 a = *(float2*)&acc[l0 * DIMV + 2 * t];
            a.x += v0.x; a.y += v0.y;
            *(float2*)&acc[l0 * DIMV + 2 * t] = a;
        }
        if (b1) {
            float2 a = *(float2*)&acc[l1 * DIMV + 2 * t];
            a.x += v1.x; a.y += v1.y;
            *(float2*)&acc[l1 * DIMV + 2 * t] = a;
        }
        if (b2) {
            float2 a = *(float2*)&acc[l2 * DIMV + 2 * t];
            a.x += v2.x; a.y += v2.y;
            *(float2*)&acc[l2 * DIMV + 2 * t] = a;
        }
        if (b3) {
            float2 a = *(float2*)&acc[l3 * DIMV + 2 * t];
            a.x += v3.x; a.y += v3.y;
            *(float2*)&acc[l3 * DIMV + 2 * t] = a;
        }
        if (t == 0) {
            scnt[l0]++;
            if (b1) scnt[l1]++;
            if (b2) scnt[l2]++;
            if (b3) scnt[l3]++;
        }
    }
    __syncthreads();

    float* dst = g_sums8 + (blockIdx.x & (NREP - 1)) * (C_NUM * DIMV);
    for (int i = t; i < C_NUM * DIMV; i += 256) atomicAdd(&dst[i], acc[i]);
    if (t < C_NUM) atomicAdd(&g_cnt[t], scnt[t]);
}

// ------------------- K3: fused centroid normalize + pair analysis (1 block, 512 thr) -----
__global__ __launch_bounds__(512) void k_cent_pairs() {
    __shared__ __align__(16) float sc[C_NUM * PSTRIDE];   // normalized centroids [c][516]
    __shared__ float spm[256];
    __shared__ float sdeg[16];
    __shared__ float scf[16];
    int t = threadIdx.x, w = t >> 5, lane = t & 31;

    // Phase A: warp w owns class w. Each lane: 16 dims strided 32, summed over 8 replicas.
    {
        int c = w;
        float cf = (float)g_cnt[c];
        float mx = fmaxf(cf, 1.f);
        float v[16];
        #pragma unroll
        for (int k = 0; k < 16; k++) v[k] = 0.f;
        #pragma unroll
        for (int rep = 0; rep < NREP; rep++) {
            const float* src = g_sums8 + rep * (C_NUM * DIMV) + c * DIMV;
            #pragma unroll
            for (int k = 0; k < 16; k++)
                v[k] += src[lane + k * 32];   // coalesced 128-B lines, L2-hot
        }
        float sq = 0.f;
        #pragma unroll
        for (int k = 0; k < 16; k++) {
            v[k] /= mx;
            sq += v[k] * v[k];
        }
        #pragma unroll
        for (int o = 16; o > 0; o >>= 1) sq += __shfl_xor_sync(0xFFFFFFFFu, sq, o);
        float inv = 1.f / fmaxf(sqrtf(sq), EPS_C);
        #pragma unroll
        for (int k = 0; k < 16; k++)
            sc[c * PSTRIDE + lane + k * 32] = v[k] * inv;
        if (lane == 0) { scf[c] = cf; g_cntf[c] = cf; }
    }
    __syncthreads();

    // write g_cnT [d][c] coalesced from smem
    for (int i = t; i < C_NUM * DIMV; i += 512) {
        int d = i >> 4, cc = i & 15;
        g_cnT[i] = sc[cc * PSTRIDE + d];
    }

    // Phase B: 256 threads = 16x16 pairs, 4 independent dot partials
    if (t < 256) {
        int i = t >> 4, j = t & 15;
        const float* ri = &sc[i * PSTRIDE];
        const float* rj = &sc[j * PSTRIDE];
        float d0 = 0.f, d1 = 0.f, d2 = 0.f, d3 = 0.f;
        #pragma unroll 4
        for (int d = 0; d < DIMV; d += 16) {
            float4 a0 = *(const float4*)(ri + d);
            float4 b0 = *(const float4*)(rj + d);
            float4 a1 = *(const float4*)(ri + d + 4);
            float4 b1 = *(const float4*)(rj + d + 4);
            float4 a2 = *(const float4*)(ri + d + 8);
            float4 b2 = *(const float4*)(rj + d + 8);
            float4 a3 = *(const float4*)(ri + d + 12);
            float4 b3 = *(const float4*)(rj + d + 12);
            d0 += a0.x * b0.x + a0.y * b0.y + a0.z * b0.z + a0.w * b0.w;
            d1 += a1.x * b1.x + a1.y * b1.y + a1.z * b1.z + a1.w * b1.w;
            d2 += a2.x * b2.x + a2.y * b2.y + a2.z * b2.z + a2.w * b2.w;
            d3 += a3.x * b3.x + a3.y * b3.y + a3.z * b3.z + a3.w * b3.w;
        }
        float dot = (d0 + d1) + (d2 + d3);
        float pd = 1.f - dot;
        float ci = scf[i], cj = scf[j];
        float pm = (i < j && ci > 0.f && cj > 0.f && pd <= BETA_C) ? 1.f : 0.f;
        spm[t] = pm;
        g_pm[t] = pm;
    }
    __syncthreads();
    if (t < 16) {
        float dg = 0.f;
        #pragma unroll
        for (int k = 0; k < 16; k++) dg += spm[t * 16 + k] + spm[k * 16 + t];
        sdeg[t] = dg;
        g_deg[t] = dg;
    }
    __syncthreads();
    if (t == 0) {
        float cnt_total = 0.f, np = 0.f;
        #pragma unroll
        for (int c = 0; c < 16; c++) cnt_total += sdeg[c] * scf[c];
        for (int k = 0; k < 256; k++) np += spm[k];
        g_count = cnt_total;
        g_numpairs = np;
    }
}

// ------------------- probe: no-op to place k_pass2 in ncu's profiled (4th) launch slot ---
__global__ void k_probe() {}

// ------------------- K4: main pass — coalesced float4 staging + R13 FFMA2 body ----------
// Tile: [512 rows][XSTR4=9 float4] (stride odd in float4 units -> STS.128 scatter and
// per-sample LDS.128 reads both conflict-free). Staging LDG.128 = 4 lines/instr (8x fewer
// L1tex wavefronts than the direct-LDG R13/R14 version, which measured L1=60.9%).
__global__ __launch_bounds__(P2_THREADS, 2) void k_pass2(const float* __restrict__ emb,
                                                         const int* __restrict__ labels, int n) {
    extern __shared__ __align__(16) float sh[];
    float4* s_x4 = (float4*)sh;                     // [512][9] float4 = 73728 B
    float*  s_c  = sh + P2_ROWS * XSTR4 * 4;        // [512][16] centroids (32 KB)
    float*  s_S  = s_c + DIMV * C_NUM;              // [16][16]
    float*  s_red = s_S + C_NUM * C_NUM;            // [4]

    int t = threadIdx.x;
    for (int i = t; i < DIMV * C_NUM / 4; i += P2_THREADS)
        ((float4*)s_c)[i] = ((const float4*)g_cnT)[i];
    s_S[t] = 0.f; s_S[t + 128] = 0.f;

    int row0 = blockIdx.x * P2_ROWS;
    int rows[P2_R];
    #pragma unroll
    for (int s = 0; s < P2_R; s++) rows[s] = row0 + t + s * P2_THREADS;

    unsigned long long acc2[P2_R][8];
    unsigned long long nrm2[P2_R];
    #pragma unroll
    for (int s = 0; s < P2_R; s++) {
        nrm2[s] = 0ull;
        #pragma unroll
        for (int c8 = 0; c8 < 8; c8++) acc2[s][c8] = 0ull;
    }

    const float4 zero4 = make_float4(0.f, 0.f, 0.f, 0.f);
    for (int ch = 0; ch < DIMV; ch += CHUNK) {
        __syncthreads();   // protects tile reuse (and s_c/s_S init on first iter)
        // stage 512 rows x 32 dims: warp-contiguous LDG.128 (4 lines/instr)
        #pragma unroll
        for (int i = 0; i < 32; i++) {
            int idx = i * P2_THREADS + t;          // 0..4095
            int rr = idx >> 3, q = idx & 7;        // row, float4-within-chunk
            int grow = row0 + rr;
            float4 v = (grow < n)
                ? __ldg((const float4*)(emb + (size_t)grow * DIMV + ch) + q)
                : zero4;
            s_x4[rr * XSTR4 + q] = v;
        }
        __syncthreads();

        #pragma unroll
        for (int d4 = 0; d4 < CHUNK; d4 += 4) {
            float4 xv[P2_R];
            #pragma unroll
            for (int s = 0; s < P2_R; s++)
                xv[s] = s_x4[(t + s * P2_THREADS) * XSTR4 + (d4 >> 2)];
            #pragma unroll
            for (int s = 0; s < P2_R; s++) {
                unsigned long long xy = pack2(xv[s].x, xv[s].y);
                unsigned long long zw = pack2(xv[s].z, xv[s].w);
                ffma2(nrm2[s], xy, xy);
                ffma2(nrm2[s], zw, zw);
            }
            const float* cb = &s_c[(ch + d4) * C_NUM];
            #pragma unroll
            for (int dd = 0; dd < 4; dd++) {
                ulonglong2 cva = *(const ulonglong2*)(cb + dd * C_NUM + 0);   // classes 0-3
                ulonglong2 cvb = *(const ulonglong2*)(cb + dd * C_NUM + 4);   // classes 4-7
                ulonglong2 cvc = *(const ulonglong2*)(cb + dd * C_NUM + 8);   // classes 8-11
                ulonglong2 cvd = *(const ulonglong2*)(cb + dd * C_NUM + 12);  // classes 12-15
                #pragma unroll
                for (int s = 0; s < P2_R; s++) {
                    float xs = (&xv[s].x)[dd];
                    unsigned long long xs2 = pack2(xs, xs);
                    ffma2(acc2[s][0], xs2, cva.x);
                    ffma2(acc2[s][1], xs2, cva.y);
                    ffma2(acc2[s][2], xs2, cvb.x);
                    ffma2(acc2[s][3], xs2, cvb.y);
                    ffma2(acc2[s][4], xs2, cvc.x);
                    ffma2(acc2[s][5], xs2, cvc.y);
                    ffma2(acc2[s][6], xs2, cvd.x);
                    ffma2(acc2[s][7], xs2, cvd.y);
                }
            }
        }
    }

    // epilogue per sample: D[c] = 1 - cn[c]·xn ; fold into intra & S
    float intra_part = 0.f;
    #pragma unroll
    for (int s = 0; s < P2_R; s++) {
        if (rows[s] < n) {
            float accf[16];
            #pragma unroll
            for (int c8 = 0; c8 < 8; c8++)
                asm("mov.b64 {%0, %1}, %2;"
                    : "=f"(accf[2 * c8]), "=f"(accf[2 * c8 + 1]) : "l"(acc2[s][c8]));
            float nlo, nhi;
            asm("mov.b64 {%0, %1}, %2;" : "=f"(nlo), "=f"(nhi) : "l"(nrm2[s]));
            float nrm = nlo + nhi;

            int lbl = __ldg(&labels[rows[s]]);
            float inv = 1.f / fmaxf(sqrtf(nrm), EPS_C);
            float down = 0.f;
            #pragma unroll
            for (int c = 0; c < 16; c++) {
                float D = 1.f - accf[c] * inv;
                float v = BETA_C - D;
                if (v > 0.f) atomicAdd(&s_S[c * 16 + lbl], v);
                if (c == lbl) down = D;
            }
            intra_part += __ldg(&g_deg[lbl]) * fmaxf(down - ALPHA_C, 0.f);
        }
    }

    #pragma unroll
    for (int o = 16; o > 0; o >>= 1)
        intra_part += __shfl_down_sync(0xFFFFFFFFu, intra_part, o);
    if ((t & 31) == 0) s_red[t >> 5] = intra_part;
    __syncthreads();   // orders s_S shared atomics before flush
    if (t == 0)
        atomicAdd(&g_intra, s_red[0] + s_red[1] + s_red[2] + s_red[3]);
    atomicAdd(&g_S[t], s_S[t]);
    atomicAdd(&g_S[t + 128], s_S[t + 128]);
}

// ------------------- K5: final scalar (block 0) + re-zero all accumulators ---------------
__global__ void k_final(float* __restrict__ out) {
    int t = threadIdx.x;   // 256
    if (blockIdx.x == 0) {
        __shared__ float sred[8];
        int i = t >> 4, j = t & 15;
        float v = g_pm[t] * (g_S[t] + g_S[j * 16 + i]);
        #pragma unroll
        for (int o = 16; o > 0; o >>= 1) v += __shfl_down_sync(0xFFFFFFFFu, v, o);
        if ((t & 31) == 0) sred[t >> 5] = v;
        __syncthreads();
        if (t == 0) {
            float inter = 0.f;
            #pragma unroll
            for (int w = 0; w < 8; w++) inter += sred[w];
            float denom = fmaxf(g_count, 1.f);
            out[0] = (g_numpairs > 0.f) ? (g_intra + inter) / denom : 0.f;
        }
        __syncthreads();   // block 0's reads of g_S/g_intra complete before re-zeroing
        g_S[t] = 0.f;
        if (t < C_NUM) g_cnt[t] = 0;
        if (t == 0) g_intra = 0.f;
    } else {
        // blocks 1..NREP zero one replica each (never read by k_final -> no race)
        float* dst = g_sums8 + (blockIdx.x - 1) * (C_NUM * DIMV);
        #pragma unroll
        for (int k = 0; k < C_NUM * DIMV / 256; k++) dst[k * 256 + t] = 0.f;
    }
}

// ------------------- launch -------------------
extern "C" void kernel_launch(void* const* d_in, const int* in_sizes, int n_in,
                              void* d_out, int out_size) {
    const float* emb    = (const float*)d_in[0];
    const int*   labels = (const int*)d_in[1];
    int n = in_sizes[1];

    int smem = (P2_ROWS * XSTR4 * 4 + DIMV * C_NUM + C_NUM * C_NUM + 4) * (int)sizeof(float);
    cudaFuncSetAttribute(k_pass2, cudaFuncAttributeMaxDynamicSharedMemorySize, smem);

    k_sums<<<K2_BLOCKS, 256>>>(emb, labels, n);
    k_cent_pairs<<<1, 512>>>();
    k_probe<<<1, 32>>>();   // keeps k_pass2 in the ncu-profiled (4th) launch slot
    int blocks = (n + P2_ROWS - 1) / P2_ROWS;
    k_pass2<<<blocks, P2_THREADS, smem>>>(emb, labels, n);
    k_final<<<1 + NREP, 256>>>((float*)d_out);
}

// round 17
// speedup vs baseline: 1.0306x; 1.0123x over previous
#include <cuda_runtime.h>
#include <math.h>

#define DIMV   512
#define C_NUM  16
#define ALPHA_C 0.1f
#define BETA_C  1.1f
#define EPS_C   1e-8f
#define K2_BLOCKS 512
#define NREP   8                       // k_sums flush replicas (contention 512 -> 64)
#define P2_THREADS 256
#define P2_R 2                         // samples per thread (occupancy > amortization)
#define P2_ROWS (P2_THREADS * P2_R)    // 512 rows per block
#define CHUNK  32                      // dims staged per iteration
#define XSTR4  9                       // tile row stride in float4 (odd -> conflict-free)
#define PSTRIDE 516                    // padded centroid row stride in k_cent_pairs smem

// ------------------- static device scratch (no allocations allowed) -------------------
// Accumulators are zero on first use (BSS) and re-zeroed at the END of every run by
// k_final -> no separate init kernel.
__device__ float g_sums8[NREP * C_NUM * DIMV];   // replicated class sums (256 KB)
__device__ int   g_cnt[C_NUM];
__device__ float g_cnT[DIMV * C_NUM];   // normalized centroids, transposed [d][c]
__device__ float g_cntf[C_NUM];
__device__ float g_deg[C_NUM];
__device__ float g_pm[C_NUM * C_NUM];
__device__ float g_S[C_NUM * C_NUM];
__device__ float g_intra;
__device__ float g_count;
__device__ float g_numpairs;

// packed f32x2 FFMA (PTX-only; ptxas never fuses from C++)
__device__ __forceinline__ void ffma2(unsigned long long& d,
                                      unsigned long long a, unsigned long long b) {
    asm("fma.rn.f32x2 %0, %1, %2, %0;" : "+l"(d) : "l"(a), "l"(b));
}
__device__ __forceinline__ unsigned long long pack2(float lo, float hi) {
    unsigned long long r;
    asm("mov.b64 %0, {%1, %2};" : "=l"(r) : "f"(lo), "f"(hi));
    return r;
}

// ------------------- K2: class sums — 512 blocks, 4-row MLP batching, replica flush ------
// Thread t exclusively owns dims {2t, 2t+1} of every class row -> no atomics in the loop.
__global__ __launch_bounds__(256) void k_sums(const float* __restrict__ emb,
                                              const int* __restrict__ labels, int n) {
    __shared__ float acc[C_NUM * DIMV];   // 32 KB
    __shared__ int   scnt[C_NUM];
    int t = threadIdx.x;
    #pragma unroll
    for (int c = 0; c < C_NUM; c++) {
        acc[c * DIMV + 2 * t]     = 0.f;
        acc[c * DIMV + 2 * t + 1] = 0.f;
    }
    if (t < C_NUM) scnt[t] = 0;
    __syncthreads();

    const float2 z2 = make_float2(0.f, 0.f);
    for (int r = blockIdx.x; r < n; r += 4 * K2_BLOCKS) {
        int r1 = r + K2_BLOCKS, r2 = r + 2 * K2_BLOCKS, r3 = r + 3 * K2_BLOCKS;
        bool b1 = r1 < n, b2 = r2 < n, b3 = r3 < n;
        int l0 = __ldg(&labels[r]);
        int l1 = b1 ? __ldg(&labels[r1]) : 0;
        int l2 = b2 ? __ldg(&labels[r2]) : 0;
        int l3 = b3 ? __ldg(&labels[r3]) : 0;
        float2 v0 = *(const float2*)(emb + (size_t)r  * DIMV + 2 * t);
        float2 v1 = b1 ? *(const float2*)(emb + (size_t)r1 * DIMV + 2 * t) : z2;
        float2 v2 = b2 ? *(const float2*)(emb + (size_t)r2 * DIMV + 2 * t) : z2;
        float2 v3 = b3 ? *(const float2*)(emb + (size_t)r3 * DIMV + 2 * t) : z2;
        {
            float2 a = *(float2*)&acc[l0 * DIMV + 2 * t];
            a.x += v0.x; a.y += v0.y;
            *(float2*)&acc[l0 * DIMV + 2 * t] = a;
        }
        if (b1) {
            float2 a = *(float2*)&acc[l1 * DIMV + 2 * t];
            a.x += v1.x; a.y += v1.y;
            *(float2*)&acc[l1 * DIMV + 2 * t] = a;
        }
        if (b2) {
            float2 a = *(float2*)&acc[l2 * DIMV + 2 * t];
            a.x += v2.x; a.y += v2.y;
            *(float2*)&acc[l2 * DIMV + 2 * t] = a;
        }
        if (b3) {
            float2 a = *(float2*)&acc[l3 * DIMV + 2 * t];
            a.x += v3.x; a.y += v3.y;
            *(float2*)&acc[l3 * DIMV + 2 * t] = a;
        }
        if (t == 0) {
            scnt[l0]++;
            if (b1) scnt[l1]++;
            if (b2) scnt[l2]++;
            if (b3) scnt[l3]++;
        }
    }
    __syncthreads();

    float* dst = g_sums8 + (blockIdx.x & (NREP - 1)) * (C_NUM * DIMV);
    for (int i = t; i < C_NUM * DIMV; i += 256) atomicAdd(&dst[i], acc[i]);
    if (t < C_NUM) atomicAdd(&g_cnt[t], scnt[t]);
}

// ------------------- K3: fused centroid normalize + pair analysis (1 block, 512 thr) -----
__global__ __launch_bounds__(512) void k_cent_pairs() {
    __shared__ __align__(16) float sc[C_NUM * PSTRIDE];   // normalized centroids [c][516]
    __shared__ float spm[256];
    __shared__ float sdeg[16];
    __shared__ float scf[16];
    int t = threadIdx.x, w = t >> 5, lane = t & 31;

    // Phase A: warp w owns class w. Each lane: 16 dims strided 32, summed over 8 replicas.
    {
        int c = w;
        float cf = (float)g_cnt[c];
        float mx = fmaxf(cf, 1.f);
        float v[16];
        #pragma unroll
        for (int k = 0; k < 16; k++) v[k] = 0.f;
        #pragma unroll
        for (int rep = 0; rep < NREP; rep++) {
            const float* src = g_sums8 + rep * (C_NUM * DIMV) + c * DIMV;
            #pragma unroll
            for (int k = 0; k < 16; k++)
                v[k] += src[lane + k * 32];   // coalesced 128-B lines, L2-hot
        }
        float sq = 0.f;
        #pragma unroll
        for (int k = 0; k < 16; k++) {
            v[k] /= mx;
            sq += v[k] * v[k];
        }
        #pragma unroll
        for (int o = 16; o > 0; o >>= 1) sq += __shfl_xor_sync(0xFFFFFFFFu, sq, o);
        float inv = 1.f / fmaxf(sqrtf(sq), EPS_C);
        #pragma unroll
        for (int k = 0; k < 16; k++)
            sc[c * PSTRIDE + lane + k * 32] = v[k] * inv;
        if (lane == 0) { scf[c] = cf; g_cntf[c] = cf; }
    }
    __syncthreads();

    // write g_cnT [d][c] coalesced from smem
    for (int i = t; i < C_NUM * DIMV; i += 512) {
        int d = i >> 4, cc = i & 15;
        g_cnT[i] = sc[cc * PSTRIDE + d];
    }

    // Phase B: 256 threads = 16x16 pairs, 4 independent dot partials
    if (t < 256) {
        int i = t >> 4, j = t & 15;
        const float* ri = &sc[i * PSTRIDE];
        const float* rj = &sc[j * PSTRIDE];
        float d0 = 0.f, d1 = 0.f, d2 = 0.f, d3 = 0.f;
        #pragma unroll 4
        for (int d = 0; d < DIMV; d += 16) {
            float4 a0 = *(const float4*)(ri + d);
            float4 b0 = *(const float4*)(rj + d);
            float4 a1 = *(const float4*)(ri + d + 4);
            float4 b1 = *(const float4*)(rj + d + 4);
            float4 a2 = *(const float4*)(ri + d + 8);
            float4 b2 = *(const float4*)(rj + d + 8);
            float4 a3 = *(const float4*)(ri + d + 12);
            float4 b3 = *(const float4*)(rj + d + 12);
            d0 += a0.x * b0.x + a0.y * b0.y + a0.z * b0.z + a0.w * b0.w;
            d1 += a1.x * b1.x + a1.y * b1.y + a1.z * b1.z + a1.w * b1.w;
            d2 += a2.x * b2.x + a2.y * b2.y + a2.z * b2.z + a2.w * b2.w;
            d3 += a3.x * b3.x + a3.y * b3.y + a3.z * b3.z + a3.w * b3.w;
        }
        float dot = (d0 + d1) + (d2 + d3);
        float pd = 1.f - dot;
        float ci = scf[i], cj = scf[j];
        float pm = (i < j && ci > 0.f && cj > 0.f && pd <= BETA_C) ? 1.f : 0.f;
        spm[t] = pm;
        g_pm[t] = pm;
    }
    __syncthreads();
    if (t < 16) {
        float dg = 0.f;
        #pragma unroll
        for (int k = 0; k < 16; k++) dg += spm[t * 16 + k] + spm[k * 16 + t];
        sdeg[t] = dg;
        g_deg[t] = dg;
    }
    __syncthreads();
    if (t == 0) {
        float cnt_total = 0.f, np = 0.f;
        #pragma unroll
        for (int c = 0; c < 16; c++) cnt_total += sdeg[c] * scf[c];
        for (int k = 0; k < 256; k++) np += spm[k];
        g_count = cnt_total;
        g_numpairs = np;
    }
}

// ------------------- probe: no-op to place k_pass2 in ncu's profiled (4th) launch slot ---
__global__ void k_probe() {}

// ------------------- K4: main pass — staged tile, P2_R=2 / 256 thr for 2x occupancy ------
// R16 showed regs=252 -> 8 warps/SM -> latency-bound at occ 10.6% with every pipe < 32%.
// Halving per-thread accumulators (P2_R=2) and doubling threads keeps work identical but
// targets <=128 regs => 16 warps/SM.
__global__ __launch_bounds__(P2_THREADS, 2) void k_pass2(const float* __restrict__ emb,
                                                         const int* __restrict__ labels, int n) {
    extern __shared__ __align__(16) float sh[];
    float4* s_x4 = (float4*)sh;                     // [512][9] float4 = 73728 B
    float*  s_c  = sh + P2_ROWS * XSTR4 * 4;        // [512][16] centroids (32 KB)
    float*  s_S  = s_c + DIMV * C_NUM;              // [16][16]
    float*  s_red = s_S + C_NUM * C_NUM;            // [8]

    int t = threadIdx.x;
    #pragma unroll
    for (int i = 0; i < DIMV * C_NUM / 4 / P2_THREADS; i++)
        ((float4*)s_c)[i * P2_THREADS + t] = ((const float4*)g_cnT)[i * P2_THREADS + t];
    s_S[t] = 0.f;

    int row0 = blockIdx.x * P2_ROWS;
    int rows[P2_R];
    #pragma unroll
    for (int s = 0; s < P2_R; s++) rows[s] = row0 + t + s * P2_THREADS;

    unsigned long long acc2[P2_R][8];
    unsigned long long nrm2[P2_R];
    #pragma unroll
    for (int s = 0; s < P2_R; s++) {
        nrm2[s] = 0ull;
        #pragma unroll
        for (int c8 = 0; c8 < 8; c8++) acc2[s][c8] = 0ull;
    }

    const float4 zero4 = make_float4(0.f, 0.f, 0.f, 0.f);
    for (int ch = 0; ch < DIMV; ch += CHUNK) {
        __syncthreads();   // protects tile reuse (and s_c/s_S init on first iter)
        // stage 512 rows x 32 dims: warp-contiguous LDG.128 (4 lines/instr)
        #pragma unroll
        for (int i = 0; i < 16; i++) {
            int idx = i * P2_THREADS + t;          // 0..4095
            int rr = idx >> 3, q = idx & 7;        // row, float4-within-chunk
            int grow = row0 + rr;
            float4 v = (grow < n)
                ? __ldg((const float4*)(emb + (size_t)grow * DIMV + ch) + q)
                : zero4;
            s_x4[rr * XSTR4 + q] = v;
        }
        __syncthreads();

        #pragma unroll
        for (int d4 = 0; d4 < CHUNK; d4 += 4) {
            float4 xv[P2_R];
            #pragma unroll
            for (int s = 0; s < P2_R; s++)
                xv[s] = s_x4[(t + s * P2_THREADS) * XSTR4 + (d4 >> 2)];
            #pragma unroll
            for (int s = 0; s < P2_R; s++) {
                unsigned long long xy = pack2(xv[s].x, xv[s].y);
                unsigned long long zw = pack2(xv[s].z, xv[s].w);
                ffma2(nrm2[s], xy, xy);
                ffma2(nrm2[s], zw, zw);
            }
            const float* cb = &s_c[(ch + d4) * C_NUM];
            #pragma unroll
            for (int dd = 0; dd < 4; dd++) {
                ulonglong2 cva = *(const ulonglong2*)(cb + dd * C_NUM + 0);   // classes 0-3
                ulonglong2 cvb = *(const ulonglong2*)(cb + dd * C_NUM + 4);   // classes 4-7
                ulonglong2 cvc = *(const ulonglong2*)(cb + dd * C_NUM + 8);   // classes 8-11
                ulonglong2 cvd = *(const ulonglong2*)(cb + dd * C_NUM + 12);  // classes 12-15
                #pragma unroll
                for (int s = 0; s < P2_R; s++) {
                    float xs = (&xv[s].x)[dd];
                    unsigned long long xs2 = pack2(xs, xs);
                    ffma2(acc2[s][0], xs2, cva.x);
                    ffma2(acc2[s][1], xs2, cva.y);
                    ffma2(acc2[s][2], xs2, cvb.x);
                    ffma2(acc2[s][3], xs2, cvb.y);
                    ffma2(acc2[s][4], xs2, cvc.x);
                    ffma2(acc2[s][5], xs2, cvc.y);
                    ffma2(acc2[s][6], xs2, cvd.x);
                    ffma2(acc2[s][7], xs2, cvd.y);
                }
            }
        }
    }

    // epilogue per sample: D[c] = 1 - cn[c]·xn ; fold into intra & S
    float intra_part = 0.f;
    #pragma unroll
    for (int s = 0; s < P2_R; s++) {
        if (rows[s] < n) {
            float accf[16];
            #pragma unroll
            for (int c8 = 0; c8 < 8; c8++)
                asm("mov.b64 {%0, %1}, %2;"
                    : "=f"(accf[2 * c8]), "=f"(accf[2 * c8 + 1]) : "l"(acc2[s][c8]));
            float nlo, nhi;
            asm("mov.b64 {%0, %1}, %2;" : "=f"(nlo), "=f"(nhi) : "l"(nrm2[s]));
            float nrm = nlo + nhi;

            int lbl = __ldg(&labels[rows[s]]);
            float inv = 1.f / fmaxf(sqrtf(nrm), EPS_C);
            float down = 0.f;
            #pragma unroll
            for (int c = 0; c < 16; c++) {
                float D = 1.f - accf[c] * inv;
                float v = BETA_C - D;
                if (v > 0.f) atomicAdd(&s_S[c * 16 + lbl], v);
                if (c == lbl) down = D;
            }
            intra_part += __ldg(&g_deg[lbl]) * fmaxf(down - ALPHA_C, 0.f);
        }
    }

    #pragma unroll
    for (int o = 16; o > 0; o >>= 1)
        intra_part += __shfl_down_sync(0xFFFFFFFFu, intra_part, o);
    if ((t & 31) == 0) s_red[t >> 5] = intra_part;
    __syncthreads();   // orders s_S shared atomics before flush
    if (t == 0) {
        float v = 0.f;
        #pragma unroll
        for (int w = 0; w < 8; w++) v += s_red[w];
        atomicAdd(&g_intra, v);
    }
    atomicAdd(&g_S[t], s_S[t]);   // 256 threads cover all 16x16 cells
}

// ------------------- K5: final scalar (block 0) + re-zero all accumulators ---------------
__global__ void k_final(float* __restrict__ out) {
    int t = threadIdx.x;   // 256
    if (blockIdx.x == 0) {
        __shared__ float sred[8];
        int i = t >> 4, j = t & 15;
        float v = g_pm[t] * (g_S[t] + g_S[j * 16 + i]);
        #pragma unroll
        for (int o = 16; o > 0; o >>= 1) v += __shfl_down_sync(0xFFFFFFFFu, v, o);
        if ((t & 31) == 0) sred[t >> 5] = v;
        __syncthreads();
        if (t == 0) {
            float inter = 0.f;
            #pragma unroll
            for (int w = 0; w < 8; w++) inter += sred[w];
            float denom = fmaxf(g_count, 1.f);
            out[0] = (g_numpairs > 0.f) ? (g_intra + inter) / denom : 0.f;
        }
        __syncthreads();   // block 0's reads of g_S/g_intra complete before re-zeroing
        g_S[t] = 0.f;
        if (t < C_NUM) g_cnt[t] = 0;
        if (t == 0) g_intra = 0.f;
    } else {
        // blocks 1..NREP zero one replica each (never read by k_final -> no race)
        float* dst = g_sums8 + (blockIdx.x - 1) * (C_NUM * DIMV);
        #pragma unroll
        for (int k = 0; k < C_NUM * DIMV / 256; k++) dst[k * 256 + t] = 0.f;
    }
}

// ------------------- launch -------------------
extern "C" void kernel_launch(void* const* d_in, const int* in_sizes, int n_in,
                              void* d_out, int out_size) {
    const float* emb    = (const float*)d_in[0];
    const int*   labels = (const int*)d_in[1];
    int n = in_sizes[1];

    int smem = (P2_ROWS * XSTR4 * 4 + DIMV * C_NUM + C_NUM * C_NUM + 8) * (int)sizeof(float);
    cudaFuncSetAttribute(k_pass2, cudaFuncAttributeMaxDynamicSharedMemorySize, smem);

    k_sums<<<K2_BLOCKS, 256>>>(emb, labels, n);
    k_cent_pairs<<<1, 512>>>();
    k_probe<<<1, 32>>>();   // keeps k_pass2 in the ncu-profiled (4th) launch slot
    int blocks = (n + P2_ROWS - 1) / P2_ROWS;
    k_pass2<<<blocks, P2_THREADS, smem>>>(emb, labels, n);
    k_final<<<1 + NREP, 256>>>((float*)d_out);
}